// round 4
// baseline (speedup 1.0000x reference)
#include <cuda_runtime.h>
#include <math.h>

#define IMG_W 8192
typedef unsigned long long ull;

// ---------------- scratch ----------------
// acc0 64x128x128 @0, acc1 64x64x64 @1048576, acc2 64x32x32 @1310720,
// acc3 64x16x16 @1376256, acc4 64x8x8 @1392640
__device__ float g_accs[1396736];
__device__ int   g_bounds[4];
__device__ float g_scale[320];
__device__ float g_shift[320];

#define FMA2(acc, a, b) asm("fma.rn.f32x2 %0, %1, %2, %0;" : "+l"(acc) : "l"(a), "l"(b))
#define UNPACK2(lo, hi, v) asm("mov.b64 {%0, %1}, %2;" : "=r"(lo), "=r"(hi) : "l"(v))

template<int L> struct Offs;
template<> struct Offs<0> { static const int v = 0; };
template<> struct Offs<1> { static const int v = 1048576; };
template<> struct Offs<2> { static const int v = 1310720; };
template<> struct Offs<3> { static const int v = 1376256; };
template<> struct Offs<4> { static const int v = 1392640; };

// ---------------- prep ----------------
__global__ void prep_kernel(const float* __restrict__ conv0_b,
                            const float* __restrict__ convs_b,
                            const float* __restrict__ gamma,
                            const float* __restrict__ beta,
                            const float* __restrict__ mean,
                            const float* __restrict__ var)
{
    int gid = blockIdx.x * blockDim.x + threadIdx.x;
    int stride = gridDim.x * blockDim.x;
    for (int k = gid; k < 348160; k += stride) g_accs[1048576 + k] = 0.0f;
    if (gid == 0) {
        g_bounds[0] = 1 << 30; g_bounds[1] = -1;
        g_bounds[2] = 1 << 30; g_bounds[3] = -1;
    }
    if (gid < 320) {
        int l = gid >> 6, c = gid & 63;
        float sc = gamma[gid] / sqrtf(var[gid] + 1e-5f);
        float b = (l == 0) ? conv0_b[c] : convs_b[(l - 1) * 64 + c];
        g_scale[gid] = sc;
        g_shift[gid] = (b - mean[gid]) * sc + beta[gid];
    }
}

// ---------------- combined row+col variance scan with early exit -----------------
__global__ void scan_kernel(const float* __restrict__ img)
{
    __shared__ int smn[256], smx[256];
    const int b = blockIdx.x, tid = threadIdx.x;
    int mn = 1 << 30, mx = -1;
    int lo_idx, hi_idx;

    if (b < 32) {
        lo_idx = 2; hi_idx = 3;
        int c = b * 256 + tid;
        float ref = img[c];
        bool found = false;
        for (int r = 1; r < IMG_W; r++) {
            found |= (img[(size_t)r * IMG_W + c] != ref);
            if (__all_sync(0xffffffffu, found)) break;
        }
        if (found) { mn = c; mx = c; }
    } else {
        lo_idx = 0; hi_idx = 1;
        int row = (b - 32) * 8 + (tid >> 5);
        int lane = tid & 31;
        const float* rowp = img + (size_t)row * IMG_W;
        float v = rowp[lane];
        float ref = __shfl_sync(0xffffffffu, v, 0);
        int flag = __any_sync(0xffffffffu, v != ref) ? 1 : 0;
        for (int base = 32; base < IMG_W && !flag; base += 32)
            flag = __any_sync(0xffffffffu, rowp[base + lane] != ref) ? 1 : 0;
        if (lane == 0 && flag) { mn = row; mx = row; }
    }

    smn[tid] = mn; smx[tid] = mx;
    __syncthreads();
    for (int s = 128; s > 0; s >>= 1) {
        if (tid < s) { smn[tid] = min(smn[tid], smn[tid + s]); smx[tid] = max(smx[tid], smx[tid + s]); }
        __syncthreads();
    }
    if (tid == 0 && smx[0] >= 0) {
        atomicMin(&g_bounds[lo_idx], smn[0]);
        atomicMax(&g_bounds[hi_idx], smx[0]);
    }
}

// ---------------- fused crop/resize + dilate + conv0 -----------------------------
__global__ void front_kernel(const float* __restrict__ img, const float* __restrict__ w0)
{
    __shared__ float s_res[37 * 37];
    __shared__ float s_dil[33 * 33];
    __shared__ float s_w[576];
    const int b = blockIdx.x, tid = threadIdx.x;
    const int ty = b >> 3, tx = b & 7;
    const int oy0 = ty * 16, ox0 = tx * 16;

    int top = g_bounds[0], bottom = g_bounds[1], left = g_bounds[2], right = g_bounds[3];
    if (bottom < 0) { top = 0; bottom = IMG_W - 1; }
    if (right  < 0) { left = 0; right  = IMG_W - 1; }

    for (int i = tid; i < 576; i += 256) s_w[i] = w0[i];

    const int ry0 = 2 * oy0 - 3, rx0 = 2 * ox0 - 3;
    const float szy = (float)(bottom - top + 1);
    const float szx = (float)(right - left + 1);
    for (int i = tid; i < 37 * 37; i += 256) {
        int r = i / 37, c = i - r * 37;
        int gy = ry0 + r, gx = rx0 + c;
        float val = 0.0f;
        if ((unsigned)gy < 256u && (unsigned)gx < 256u) {
            float cy = (float)top  + ((float)gy + 0.5f) * szy * (1.0f / 256.0f) - 0.5f;
            float cx = (float)left + ((float)gx + 0.5f) * szx * (1.0f / 256.0f) - 0.5f;
            float fy0 = floorf(cy), fx0 = floorf(cx);
            float wy = cy - fy0, wx = cx - fx0;
            int y0 = (int)fminf(fmaxf(fy0,        (float)top),  (float)bottom);
            int y1 = (int)fminf(fmaxf(fy0 + 1.0f, (float)top),  (float)bottom);
            int x0 = (int)fminf(fmaxf(fx0,        (float)left), (float)right);
            int x1 = (int)fminf(fmaxf(fx0 + 1.0f, (float)left), (float)right);
            float v00 = img[(size_t)y0 * IMG_W + x0];
            float v01 = img[(size_t)y0 * IMG_W + x1];
            float v10 = img[(size_t)y1 * IMG_W + x0];
            float v11 = img[(size_t)y1 * IMG_W + x1];
            float tr = v00 * (1.0f - wx) + v01 * wx;
            float br = v10 * (1.0f - wx) + v11 * wx;
            val = 255.0f - (tr * (1.0f - wy) + br * wy);
        }
        s_res[i] = val;
    }
    __syncthreads();

    for (int i = tid; i < 33 * 33; i += 256) {
        int r = i / 33, c = i - r * 33;
        int gy = 2 * oy0 - 1 + r, gx = 2 * ox0 - 1 + c;
        float val = 0.0f;
        if ((unsigned)gy < 256u && (unsigned)gx < 256u) {
            float s = 0.0f;
            #pragma unroll
            for (int dy = 0; dy <= 4; dy += 2)
                #pragma unroll
                for (int dx = 0; dx <= 4; dx += 2)
                    s += s_res[(r + dy) * 37 + (c + dx)];
            val = 255.0f - fminf(fmaxf(s, 0.0f), 255.0f);
        }
        s_dil[i] = val;
    }
    __syncthreads();

    const int ly = tid >> 4, lx = tid & 15;
    float v[9];
    #pragma unroll
    for (int ky = 0; ky < 3; ky++)
        #pragma unroll
        for (int kx = 0; kx < 3; kx++)
            v[ky * 3 + kx] = s_dil[(2 * ly + ky) * 33 + (2 * lx + kx)];

    const int oy = oy0 + ly, ox = ox0 + lx;
    #pragma unroll 4
    for (int oc = 0; oc < 64; oc++) {
        float a = 0.0f;
        #pragma unroll
        for (int k = 0; k < 9; k++) a = fmaf(v[k], s_w[oc * 9 + k], a);
        g_accs[(oc * 128 + oy) * 128 + ox] = a;
    }
}

// ---------------- 64->64 conv via even/odd phase decomposition -------------------
// stride-2 3x3 conv: out[x] = w0*e[x] + w1*o[x] + w2*es[x] with e[i]=in[2i],
// o[i]=in[2i+1], es[i]=in[2i+2] stored as separate smem arrays -> adjacent output
// pairs consume ALIGNED f32x2 pairs directly from LDS.128, zero register packing.
// Weights stored pre-duplicated {w,w} in smem -> broadcast operand also load-only.
// Block 256 thr: 16 oc-groups(4 oc) x 16 px-groups(1 row x 8 px). Tile 8x16 out.
template<int LAYER, int ICS>
__global__ void __launch_bounds__(256) conv_eo_kernel(const float* __restrict__ convs_w)
{
    constexpr int HIN  = 256 >> LAYER;
    constexpr int HOUT = HIN >> 1;
    constexpr int TILESX = (HOUT >= 16) ? (HOUT / 16) : 1;
    // smem row layout per (icc, r): e[17] @0, o[16] @20, es[16] @36, stride 52
    constexpr int RSTR = 52, CSTR = 17 * RSTR;   // 884 floats per channel

    const int tile = blockIdx.x;
    const int ty = tile / TILESX, tx = tile - ty * TILESX;
    const int oy0 = ty * 8, ox0 = tx * 16;
    const int ic0 = blockIdx.y * ICS;

    const float* __restrict__ in  = g_accs + Offs<LAYER - 1>::v;
    float* __restrict__ out       = g_accs + Offs<LAYER>::v;
    const float* __restrict__ w   = convs_w + (LAYER - 1) * 36864;
    const float* __restrict__ scl = g_scale + (LAYER - 1) * 64;
    const float* __restrict__ shf = g_shift + (LAYER - 1) * 64;

    __shared__ __align__(16) float s_w[ICS * 9 * 128];   // [(icc*9+k)*128 + oc*2 + d]
    __shared__ __align__(16) float s_in[ICS * CSTR];

    const int tid = threadIdx.x;

    // stage weights, duplicated
    for (int idx = tid; idx < ICS * 9 * 64; idx += 256) {
        int icc = idx / 576, rem = idx - icc * 576;
        int k = rem >> 6, oc = rem & 63;
        float val = w[oc * 576 + (ic0 + icc) * 9 + k];
        s_w[(icc * 9 + k) * 128 + oc * 2]     = val;
        s_w[(icc * 9 + k) * 128 + oc * 2 + 1] = val;
    }

    // stage input window (17 x 33) into e/o/es phase arrays, fused bias+BN+ReLU
    const int iy0 = oy0 * 2 - 1, ix0 = ox0 * 2 - 1;
    for (int idx = tid; idx < ICS * 17 * 33; idx += 256) {
        int icc = idx / 561, pos = idx - icc * 561;
        int r = pos / 33, c = pos - r * 33;
        int ic = ic0 + icc;
        int gy = iy0 + r, gx = ix0 + c;
        float vv = 0.0f;
        if ((unsigned)gy < (unsigned)HIN && (unsigned)gx < (unsigned)HIN)
            vv = fmaxf(fmaf(in[ic * HIN * HIN + gy * HIN + gx], scl[ic], shf[ic]), 0.0f);
        int base = icc * CSTR + r * RSTR;
        int h = c >> 1;
        if (c & 1) s_in[base + 20 + h] = vv;            // o[h]
        else {
            s_in[base + h] = vv;                        // e[h]
            if (c >= 2) s_in[base + 36 + h - 1] = vv;   // es[h-1]
        }
    }
    __syncthreads();

    const int ocg = tid >> 4;          // warp-uniform -> weight loads broadcast
    const int grp = tid & 15;
    const int lry = grp >> 1;          // local output row 0..7
    const int x0l = (grp & 1) * 8;     // local col base 0 or 8

    ull acc[4][4];
    #pragma unroll
    for (int j = 0; j < 4; j++)
        #pragma unroll
        for (int p = 0; p < 4; p++) acc[j][p] = 0ull;

    #pragma unroll
    for (int icc = 0; icc < ICS; icc++) {
        #pragma unroll
        for (int ky = 0; ky < 3; ky++) {
            const float* rowb = s_in + icc * CSTR + (2 * lry + ky) * RSTR;
            ulonglong2 E01 = *reinterpret_cast<const ulonglong2*>(rowb + x0l);
            ulonglong2 E23 = *reinterpret_cast<const ulonglong2*>(rowb + x0l + 4);
            ulonglong2 O01 = *reinterpret_cast<const ulonglong2*>(rowb + 20 + x0l);
            ulonglong2 O23 = *reinterpret_cast<const ulonglong2*>(rowb + 20 + x0l + 4);
            ulonglong2 S01 = *reinterpret_cast<const ulonglong2*>(rowb + 36 + x0l);
            ulonglong2 S23 = *reinterpret_cast<const ulonglong2*>(rowb + 36 + x0l + 4);
            ull V[3][4] = {{E01.x, E01.y, E23.x, E23.y},
                           {O01.x, O01.y, O23.x, O23.y},
                           {S01.x, S01.y, S23.x, S23.y}};
            #pragma unroll
            for (int kx = 0; kx < 3; kx++) {
                const float* wb = s_w + (icc * 9 + ky * 3 + kx) * 128 + ocg * 8;
                ulonglong2 Wa = *reinterpret_cast<const ulonglong2*>(wb);      // {w0,w0},{w1,w1}
                ulonglong2 Wb = *reinterpret_cast<const ulonglong2*>(wb + 4);  // {w2,w2},{w3,w3}
                #pragma unroll
                for (int p = 0; p < 4; p++) {
                    FMA2(acc[0][p], V[kx][p], Wa.x);
                    FMA2(acc[1][p], V[kx][p], Wa.y);
                    FMA2(acc[2][p], V[kx][p], Wb.x);
                    FMA2(acc[3][p], V[kx][p], Wb.y);
                }
            }
        }
    }

    const int oy = oy0 + lry;
    #pragma unroll
    for (int j = 0; j < 4; j++) {
        int oc = ocg * 4 + j;
        #pragma unroll
        for (int p = 0; p < 4; p++) {
            unsigned lo, hi;
            UNPACK2(lo, hi, acc[j][p]);
            int ox = ox0 + x0l + 2 * p;
            if (ox < HOUT) {   // only binds for HOUT==8 (conv4)
                atomicAdd(&out[(oc * HOUT + oy) * HOUT + ox],     __uint_as_float(lo));
                atomicAdd(&out[(oc * HOUT + oy) * HOUT + ox + 1], __uint_as_float(hi));
            }
        }
    }
}

// ---------------- head ----------------
__global__ void head_kernel(const float* __restrict__ head_w,
                            const float* __restrict__ head_b,
                            int* __restrict__ out)
{
    int c = threadIdx.x;
    const float* a4 = g_accs + 1392640;
    float sc = g_scale[256 + c], sh = g_shift[256 + c];
    float s = 0.0f;
    #pragma unroll 8
    for (int p = 0; p < 64; p++) s += fmaxf(fmaf(a4[c * 64 + p], sc, sh), 0.0f);
    float feat = s * (1.0f / 64.0f);
    __shared__ float l0[64], l1[64];
    l0[c] = feat * head_w[c];
    l1[c] = feat * head_w[64 + c];
    __syncthreads();
    if (c == 0) {
        float A = head_b[0], B = head_b[1];
        for (int i = 0; i < 64; i++) { A += l0[i]; B += l1[i]; }
        out[0] = (B > A) ? 1 : 0;
    }
}

// ---------------- launch (8 graph nodes) ----------------
extern "C" void kernel_launch(void* const* d_in, const int* in_sizes, int n_in,
                              void* d_out, int out_size)
{
    const float* image   = (const float*)d_in[0];
    const float* conv0_w = (const float*)d_in[1];
    const float* conv0_b = (const float*)d_in[2];
    const float* convs_w = (const float*)d_in[3];
    const float* convs_b = (const float*)d_in[4];
    const float* bn_g    = (const float*)d_in[5];
    const float* bn_b    = (const float*)d_in[6];
    const float* bn_m    = (const float*)d_in[7];
    const float* bn_v    = (const float*)d_in[8];
    const float* head_w  = (const float*)d_in[9];
    const float* head_b  = (const float*)d_in[10];
    int* outp = (int*)d_out;

    prep_kernel<<<256, 256>>>(conv0_b, convs_b, bn_g, bn_b, bn_m, bn_v);
    scan_kernel<<<1056, 256>>>(image);
    front_kernel<<<64, 256>>>(image, conv0_w);
    conv_eo_kernel<1, 4><<<dim3(32, 16), 256>>>(convs_w);  // 128->64, 512 blocks
    conv_eo_kernel<2, 4><<<dim3( 8, 16), 256>>>(convs_w);  // 64->32,  128 blocks
    conv_eo_kernel<3, 2><<<dim3( 2, 32), 256>>>(convs_w);  // 32->16,   64 blocks
    conv_eo_kernel<4, 2><<<dim3( 1, 32), 256>>>(convs_w);  // 16->8,    32 blocks
    head_kernel<<<1, 64>>>(head_w, head_b, outp);
}

// round 5
// speedup vs baseline: 1.3547x; 1.3547x over previous
#include <cuda_runtime.h>
#include <math.h>

#define IMG_W 8192
typedef unsigned long long ull;

// ---------------- scratch ----------------
// acc0 64x128x128 @0, acc1 64x64x64 @1048576, acc2 64x32x32 @1310720,
// acc3 64x16x16 @1376256, acc4 64x8x8 @1392640
__device__ float g_accs[1396736];
__device__ int   g_bounds[4];
__device__ float g_scale[320];
__device__ float g_shift[320];

#define FMA2(acc, a, b) asm("fma.rn.f32x2 %0, %1, %2, %0;" : "+l"(acc) : "l"(a), "l"(b))
#define UNPACK2(lo, hi, v) asm("mov.b64 {%0, %1}, %2;" : "=r"(lo), "=r"(hi) : "l"(v))

template<int L> struct Offs;
template<> struct Offs<0> { static const int v = 0; };
template<> struct Offs<1> { static const int v = 1048576; };
template<> struct Offs<2> { static const int v = 1310720; };
template<> struct Offs<3> { static const int v = 1376256; };
template<> struct Offs<4> { static const int v = 1392640; };

// ---------------- prep ----------------
__global__ void prep_kernel(const float* __restrict__ conv0_b,
                            const float* __restrict__ convs_b,
                            const float* __restrict__ gamma,
                            const float* __restrict__ beta,
                            const float* __restrict__ mean,
                            const float* __restrict__ var)
{
    int gid = blockIdx.x * blockDim.x + threadIdx.x;
    int stride = gridDim.x * blockDim.x;
    for (int k = gid; k < 348160; k += stride) g_accs[1048576 + k] = 0.0f;
    if (gid == 0) {
        g_bounds[0] = 1 << 30; g_bounds[1] = -1;
        g_bounds[2] = 1 << 30; g_bounds[3] = -1;
    }
    if (gid < 320) {
        int l = gid >> 6, c = gid & 63;
        float sc = gamma[gid] / sqrtf(var[gid] + 1e-5f);
        float b = (l == 0) ? conv0_b[c] : convs_b[(l - 1) * 64 + c];
        g_scale[gid] = sc;
        g_shift[gid] = (b - mean[gid]) * sc + beta[gid];
    }
}

// ---------------- combined row+col variance scan with early exit -----------------
__global__ void scan_kernel(const float* __restrict__ img)
{
    __shared__ int smn[256], smx[256];
    const int b = blockIdx.x, tid = threadIdx.x;
    int mn = 1 << 30, mx = -1;
    int lo_idx, hi_idx;

    if (b < 32) {
        lo_idx = 2; hi_idx = 3;
        int c = b * 256 + tid;
        float ref = img[c];
        bool found = false;
        for (int r = 1; r < IMG_W; r++) {
            found |= (img[(size_t)r * IMG_W + c] != ref);
            if (__all_sync(0xffffffffu, found)) break;
        }
        if (found) { mn = c; mx = c; }
    } else {
        lo_idx = 0; hi_idx = 1;
        int row = (b - 32) * 8 + (tid >> 5);
        int lane = tid & 31;
        const float* rowp = img + (size_t)row * IMG_W;
        float v = rowp[lane];
        float ref = __shfl_sync(0xffffffffu, v, 0);
        int flag = __any_sync(0xffffffffu, v != ref) ? 1 : 0;
        for (int base = 32; base < IMG_W && !flag; base += 32)
            flag = __any_sync(0xffffffffu, rowp[base + lane] != ref) ? 1 : 0;
        if (lane == 0 && flag) { mn = row; mx = row; }
    }

    smn[tid] = mn; smx[tid] = mx;
    __syncthreads();
    for (int s = 128; s > 0; s >>= 1) {
        if (tid < s) { smn[tid] = min(smn[tid], smn[tid + s]); smx[tid] = max(smx[tid], smx[tid + s]); }
        __syncthreads();
    }
    if (tid == 0 && smx[0] >= 0) {
        atomicMin(&g_bounds[lo_idx], smn[0]);
        atomicMax(&g_bounds[hi_idx], smx[0]);
    }
}

// ---------------- fused crop/resize + dilate + conv0 -----------------------------
__global__ void front_kernel(const float* __restrict__ img, const float* __restrict__ w0)
{
    __shared__ float s_res[37 * 37];
    __shared__ float s_dil[33 * 33];
    __shared__ float s_w[576];
    const int b = blockIdx.x, tid = threadIdx.x;
    const int ty = b >> 3, tx = b & 7;
    const int oy0 = ty * 16, ox0 = tx * 16;

    int top = g_bounds[0], bottom = g_bounds[1], left = g_bounds[2], right = g_bounds[3];
    if (bottom < 0) { top = 0; bottom = IMG_W - 1; }
    if (right  < 0) { left = 0; right  = IMG_W - 1; }

    for (int i = tid; i < 576; i += 256) s_w[i] = w0[i];

    const int ry0 = 2 * oy0 - 3, rx0 = 2 * ox0 - 3;
    const float szy = (float)(bottom - top + 1);
    const float szx = (float)(right - left + 1);
    for (int i = tid; i < 37 * 37; i += 256) {
        int r = i / 37, c = i - r * 37;
        int gy = ry0 + r, gx = rx0 + c;
        float val = 0.0f;
        if ((unsigned)gy < 256u && (unsigned)gx < 256u) {
            float cy = (float)top  + ((float)gy + 0.5f) * szy * (1.0f / 256.0f) - 0.5f;
            float cx = (float)left + ((float)gx + 0.5f) * szx * (1.0f / 256.0f) - 0.5f;
            float fy0 = floorf(cy), fx0 = floorf(cx);
            float wy = cy - fy0, wx = cx - fx0;
            int y0 = (int)fminf(fmaxf(fy0,        (float)top),  (float)bottom);
            int y1 = (int)fminf(fmaxf(fy0 + 1.0f, (float)top),  (float)bottom);
            int x0 = (int)fminf(fmaxf(fx0,        (float)left), (float)right);
            int x1 = (int)fminf(fmaxf(fx0 + 1.0f, (float)left), (float)right);
            float v00 = img[(size_t)y0 * IMG_W + x0];
            float v01 = img[(size_t)y0 * IMG_W + x1];
            float v10 = img[(size_t)y1 * IMG_W + x0];
            float v11 = img[(size_t)y1 * IMG_W + x1];
            float tr = v00 * (1.0f - wx) + v01 * wx;
            float br = v10 * (1.0f - wx) + v11 * wx;
            val = 255.0f - (tr * (1.0f - wy) + br * wy);
        }
        s_res[i] = val;
    }
    __syncthreads();

    for (int i = tid; i < 33 * 33; i += 256) {
        int r = i / 33, c = i - r * 33;
        int gy = 2 * oy0 - 1 + r, gx = 2 * ox0 - 1 + c;
        float val = 0.0f;
        if ((unsigned)gy < 256u && (unsigned)gx < 256u) {
            float s = 0.0f;
            #pragma unroll
            for (int dy = 0; dy <= 4; dy += 2)
                #pragma unroll
                for (int dx = 0; dx <= 4; dx += 2)
                    s += s_res[(r + dy) * 37 + (c + dx)];
            val = 255.0f - fminf(fmaxf(s, 0.0f), 255.0f);
        }
        s_dil[i] = val;
    }
    __syncthreads();

    const int ly = tid >> 4, lx = tid & 15;
    float v[9];
    #pragma unroll
    for (int ky = 0; ky < 3; ky++)
        #pragma unroll
        for (int kx = 0; kx < 3; kx++)
            v[ky * 3 + kx] = s_dil[(2 * ly + ky) * 33 + (2 * lx + kx)];

    const int oy = oy0 + ly, ox = ox0 + lx;
    #pragma unroll 4
    for (int oc = 0; oc < 64; oc++) {
        float a = 0.0f;
        #pragma unroll
        for (int k = 0; k < 9; k++) a = fmaf(v[k], s_w[oc * 9 + k], a);
        g_accs[(oc * 128 + oy) * 128 + ox] = a;
    }
}

// ---------------- 64->64 conv, ic-PAIR-packed f32x2 (zero packing MOVs) ----------
// acc f32x2 accumulates {even-ic partial, odd-ic partial}; output = lo + hi.
// Input smem: per ic-pair, 17x17 window stored channel-interleaved [r][c][ich]
// (float2 per pixel, rows padded to 36 floats -> col groups 16B aligned).
// Weights smem: [(pair*9+k)*128 + oc*2 + ich] -> one LDS.128 = 2 ocs x 2 ics.
// Block 256: 16 oc-groups(4 oc) x 16 spatial slots (2x2 micro in 8x8 tile).
template<int LAYER, int ICS>
__global__ void __launch_bounds__(256) conv_pp_kernel(const float* __restrict__ convs_w)
{
    constexpr int HIN  = 256 >> LAYER;
    constexpr int HOUT = HIN >> 1;
    constexpr int TILESX = HOUT >> 3;
    constexpr int PAIRS = ICS / 2;
    constexpr int RSTR = 36;             // floats per row (17 px * 2 ic, pad to 36)
    constexpr int CSTR = 17 * RSTR;      // floats per ic-pair window

    const int tile = blockIdx.x;
    const int ty = tile / TILESX, tx = tile - ty * TILESX;
    const int oy0 = ty * 8, ox0 = tx * 8;
    const int ic0 = blockIdx.y * ICS;

    const float* __restrict__ in  = g_accs + Offs<LAYER - 1>::v;
    float* __restrict__ out       = g_accs + Offs<LAYER>::v;
    const float* __restrict__ w   = convs_w + (LAYER - 1) * 36864;
    const float* __restrict__ scl = g_scale + (LAYER - 1) * 64;
    const float* __restrict__ shf = g_shift + (LAYER - 1) * 64;

    __shared__ __align__(16) float s_w[ICS * 576];     // [(P*9+k)*128 + oc*2 + ich]
    __shared__ __align__(16) float s_in[PAIRS * CSTR];

    const int tid = threadIdx.x;

    // stage weights, ic-pair interleaved
    for (int idx = tid; idx < ICS * 576; idx += 256) {
        int oc = idx / (ICS * 9);
        int rem = idx - oc * (ICS * 9);
        int ic = rem / 9, k = rem - ic * 9;
        float val = w[oc * 576 + (ic0 + ic) * 9 + k];
        s_w[((ic >> 1) * 9 + k) * 128 + oc * 2 + (ic & 1)] = val;
    }

    // stage input windows (17x17 per ic), fused bias+BN+ReLU, pair-interleaved
    const int iy0 = oy0 * 2 - 1, ix0 = ox0 * 2 - 1;
    for (int idx = tid; idx < ICS * 289; idx += 256) {
        int ch = idx / 289, pos = idx - ch * 289;
        int r = pos / 17, c = pos - r * 17;
        int ic = ic0 + ch;
        int gy = iy0 + r, gx = ix0 + c;
        float vv = 0.0f;
        if ((unsigned)gy < (unsigned)HIN && (unsigned)gx < (unsigned)HIN)
            vv = fmaxf(fmaf(in[ic * HIN * HIN + gy * HIN + gx], scl[ic], shf[ic]), 0.0f);
        s_in[(ch >> 1) * CSTR + r * RSTR + c * 2 + (ch & 1)] = vv;
    }
    __syncthreads();   // the only barrier

    const int ocg = tid & 15;
    const int sps = tid >> 4;
    const int my = sps >> 2, mx = sps & 3;

    ull acc[4][4];     // [j: oc ocg*4+j][p: py*2+px]
    #pragma unroll
    for (int j = 0; j < 4; j++)
        #pragma unroll
        for (int p = 0; p < 4; p++) acc[j][p] = 0ull;

    #pragma unroll
    for (int P = 0; P < PAIRS; P++) {
        const float* base = s_in + P * CSTR + 8 * mx;   // 32B-aligned col group
        #pragma unroll
        for (int ky = 0; ky < 3; ky++) {
            // rowA feeds py=0 (input row 4my+ky), rowB feeds py=1 (row 4my+ky+2)
            const float* ra = base + (4 * my + ky) * RSTR;
            const float* rb = ra + 2 * RSTR;
            ulonglong2 A01 = *reinterpret_cast<const ulonglong2*>(ra);
            ulonglong2 A23 = *reinterpret_cast<const ulonglong2*>(ra + 4);
            ull A4 = *reinterpret_cast<const ull*>(ra + 8);
            ulonglong2 B01 = *reinterpret_cast<const ulonglong2*>(rb);
            ulonglong2 B23 = *reinterpret_cast<const ulonglong2*>(rb + 4);
            ull B4 = *reinterpret_cast<const ull*>(rb + 8);
            ull Ar[5] = {A01.x, A01.y, A23.x, A23.y, A4};
            ull Br[5] = {B01.x, B01.y, B23.x, B23.y, B4};
            #pragma unroll
            for (int kx = 0; kx < 3; kx++) {
                const float* wb = s_w + ((P * 9 + ky * 3 + kx) * 128) + ocg * 8;
                ulonglong2 Wa = *reinterpret_cast<const ulonglong2*>(wb);
                ulonglong2 Wb = *reinterpret_cast<const ulonglong2*>(wb + 4);
                ull W[4] = {Wa.x, Wa.y, Wb.x, Wb.y};
                #pragma unroll
                for (int px = 0; px < 2; px++) {
                    ull vA = Ar[kx + 2 * px];
                    ull vB = Br[kx + 2 * px];
                    #pragma unroll
                    for (int j = 0; j < 4; j++) {
                        FMA2(acc[j][px],     vA, W[j]);
                        FMA2(acc[j][2 + px], vB, W[j]);
                    }
                }
            }
        }
    }

    #pragma unroll
    for (int j = 0; j < 4; j++) {
        const int oc = ocg * 4 + j;
        #pragma unroll
        for (int p = 0; p < 4; p++) {
            unsigned lo, hi;
            UNPACK2(lo, hi, acc[j][p]);
            float v = __uint_as_float(lo) + __uint_as_float(hi);  // even-ic + odd-ic
            int oy = oy0 + 2 * my + (p >> 1);
            int ox = ox0 + 2 * mx + (p & 1);
            atomicAdd(&out[(oc * HOUT + oy) * HOUT + ox], v);
        }
    }
}

// ---------------- head ----------------
__global__ void head_kernel(const float* __restrict__ head_w,
                            const float* __restrict__ head_b,
                            int* __restrict__ out)
{
    int c = threadIdx.x;
    const float* a4 = g_accs + 1392640;
    float sc = g_scale[256 + c], sh = g_shift[256 + c];
    float s = 0.0f;
    #pragma unroll 8
    for (int p = 0; p < 64; p++) s += fmaxf(fmaf(a4[c * 64 + p], sc, sh), 0.0f);
    float feat = s * (1.0f / 64.0f);
    __shared__ float l0[64], l1[64];
    l0[c] = feat * head_w[c];
    l1[c] = feat * head_w[64 + c];
    __syncthreads();
    if (c == 0) {
        float A = head_b[0], B = head_b[1];
        for (int i = 0; i < 64; i++) { A += l0[i]; B += l1[i]; }
        out[0] = (B > A) ? 1 : 0;
    }
}

// ---------------- launch (8 graph nodes) ----------------
extern "C" void kernel_launch(void* const* d_in, const int* in_sizes, int n_in,
                              void* d_out, int out_size)
{
    const float* image   = (const float*)d_in[0];
    const float* conv0_w = (const float*)d_in[1];
    const float* conv0_b = (const float*)d_in[2];
    const float* convs_w = (const float*)d_in[3];
    const float* convs_b = (const float*)d_in[4];
    const float* bn_g    = (const float*)d_in[5];
    const float* bn_b    = (const float*)d_in[6];
    const float* bn_m    = (const float*)d_in[7];
    const float* bn_v    = (const float*)d_in[8];
    const float* head_w  = (const float*)d_in[9];
    const float* head_b  = (const float*)d_in[10];
    int* outp = (int*)d_out;

    prep_kernel<<<256, 256>>>(conv0_b, convs_b, bn_g, bn_b, bn_m, bn_v);
    scan_kernel<<<1056, 256>>>(image);
    front_kernel<<<64, 256>>>(image, conv0_w);
    conv_pp_kernel<1, 8><<<dim3(64,  8), 256>>>(convs_w);  // 128->64, 512 blocks
    conv_pp_kernel<2, 8><<<dim3(16,  8), 256>>>(convs_w);  // 64->32,  128 blocks
    conv_pp_kernel<3, 4><<<dim3( 4, 16), 256>>>(convs_w);  // 32->16,   64 blocks
    conv_pp_kernel<4, 2><<<dim3( 1, 32), 256>>>(convs_w);  // 16->8,    32 blocks
    head_kernel<<<1, 64>>>(head_w, head_b, outp);
}